// round 1
// baseline (speedup 1.0000x reference)
#include <cuda_runtime.h>
#include <math.h>

// Problem dims (fixed)
#define BB 1024   // batch
#define SS 128    // seq len
#define EE 512    // embed dim
#define HH 1024   // hidden
#define GG 4096   // 4*H (gates)
#define NN 4096   // output dim

// Scratch (device globals; zero-initialized at module load)
__device__ float g_embs[(size_t)SS * BB * EE];   // time-major [S,B,E], 256 MB
__device__ float g_gates[(size_t)BB * GG];       // 16 MB
__device__ float g_h[BB * HH];                   // 4 MB
__device__ float g_c[BB * HH];                   // 4 MB
__device__ float g_zero[NN];                     // zero bias

// ---------------------------------------------------------------------------
// Embedding gather: embs[s*B+b, :] = emb_table[m[b,S..], :]
// grid = S*B blocks, 128 threads, one float4 per thread (E=512 floats)
// ---------------------------------------------------------------------------
__global__ void gather_kernel(const int* __restrict__ m,
                              const float* __restrict__ tab) {
    int blk = blockIdx.x;           // = s*B + b
    int s = blk >> 10;              // B = 1024
    int b = blk & 1023;
    int tok = m[b * SS + s];        // m is [B,S] row-major
    const float4* src = (const float4*)(tab + (size_t)tok * EE);
    float4* dst = (float4*)(g_embs + (size_t)blk * EE);
    dst[threadIdx.x] = src[threadIdx.x];
}

__global__ void zero_hc_kernel() {
    int i = blockIdx.x * blockDim.x + threadIdx.x;
    g_h[i] = 0.0f;
    g_c[i] = 0.0f;
}

// ---------------------------------------------------------------------------
// NT SGEMM: C[m,n] = sum_k A[m,k]*B[n,k] + bias1[n] + bias2[n]
// SPLIT=true: k < Ksplit reads (A1,B1), k >= Ksplit reads (A2,B2) at col k-Ksplit.
// BM=BN=128, BK=16, 256 threads, 8x8 per thread.
// ---------------------------------------------------------------------------
template <bool SPLIT>
__global__ __launch_bounds__(256) void gemm_nt(
    const float* __restrict__ A1, int lda1,
    const float* __restrict__ A2, int lda2,
    const float* __restrict__ B1, int ldb1,
    const float* __restrict__ B2, int ldb2,
    int Ksplit, int K,
    const float* __restrict__ bias1,
    const float* __restrict__ bias2,
    float* __restrict__ C, int N) {

    __shared__ float As[16][132];   // padded to avoid smem store conflicts
    __shared__ float Bs[16][132];

    const int tid = threadIdx.x;
    const int lr  = tid >> 2;       // loader row 0..63
    const int lc4 = tid & 3;        // loader col-quad 0..3
    const int tr  = tid >> 4;       // compute row 0..15
    const int tc  = tid & 15;       // compute col 0..15

    const int rowBase = blockIdx.y * 128;
    const int colBase = blockIdx.x * 128;

    float acc[8][8];
#pragma unroll
    for (int i = 0; i < 8; i++)
#pragma unroll
        for (int j = 0; j < 8; j++) acc[i][j] = 0.0f;

    for (int k0 = 0; k0 < K; k0 += 16) {
        const float* Ap; const float* Bp;
        int la, lb, kk;
        if (!SPLIT || k0 < Ksplit) {
            Ap = A1; la = lda1; Bp = B1; lb = ldb1; kk = k0;
        } else {
            Ap = A2; la = lda2; Bp = B2; lb = ldb2; kk = k0 - Ksplit;
        }
        // global -> regs
        float4 a0 = *(const float4*)(Ap + (size_t)(rowBase + lr) * la + kk + lc4 * 4);
        float4 a1 = *(const float4*)(Ap + (size_t)(rowBase + lr + 64) * la + kk + lc4 * 4);
        float4 b0 = *(const float4*)(Bp + (size_t)(colBase + lr) * lb + kk + lc4 * 4);
        float4 b1 = *(const float4*)(Bp + (size_t)(colBase + lr + 64) * lb + kk + lc4 * 4);

        __syncthreads();
        As[lc4 * 4 + 0][lr] = a0.x;  As[lc4 * 4 + 1][lr] = a0.y;
        As[lc4 * 4 + 2][lr] = a0.z;  As[lc4 * 4 + 3][lr] = a0.w;
        As[lc4 * 4 + 0][lr + 64] = a1.x;  As[lc4 * 4 + 1][lr + 64] = a1.y;
        As[lc4 * 4 + 2][lr + 64] = a1.z;  As[lc4 * 4 + 3][lr + 64] = a1.w;
        Bs[lc4 * 4 + 0][lr] = b0.x;  Bs[lc4 * 4 + 1][lr] = b0.y;
        Bs[lc4 * 4 + 2][lr] = b0.z;  Bs[lc4 * 4 + 3][lr] = b0.w;
        Bs[lc4 * 4 + 0][lr + 64] = b1.x;  Bs[lc4 * 4 + 1][lr + 64] = b1.y;
        Bs[lc4 * 4 + 2][lr + 64] = b1.z;  Bs[lc4 * 4 + 3][lr + 64] = b1.w;
        __syncthreads();

#pragma unroll
        for (int k = 0; k < 16; ++k) {
            float4 av0 = *(const float4*)&As[k][tr * 8];
            float4 av1 = *(const float4*)&As[k][tr * 8 + 4];
            float4 bv0 = *(const float4*)&Bs[k][tc * 8];
            float4 bv1 = *(const float4*)&Bs[k][tc * 8 + 4];
            float ar[8] = {av0.x, av0.y, av0.z, av0.w, av1.x, av1.y, av1.z, av1.w};
            float br[8] = {bv0.x, bv0.y, bv0.z, bv0.w, bv1.x, bv1.y, bv1.z, bv1.w};
#pragma unroll
            for (int i = 0; i < 8; i++)
#pragma unroll
                for (int j = 0; j < 8; j++) acc[i][j] += ar[i] * br[j];
        }
    }

    // epilogue
    const int row0 = rowBase + tr * 8;
    const int col0 = colBase + tc * 8;
    float bsum[8];
#pragma unroll
    for (int j = 0; j < 8; j++) bsum[j] = bias1[col0 + j] + bias2[col0 + j];
#pragma unroll
    for (int i = 0; i < 8; i++) {
        float4 v0, v1;
        v0.x = acc[i][0] + bsum[0]; v0.y = acc[i][1] + bsum[1];
        v0.z = acc[i][2] + bsum[2]; v0.w = acc[i][3] + bsum[3];
        v1.x = acc[i][4] + bsum[4]; v1.y = acc[i][5] + bsum[5];
        v1.z = acc[i][6] + bsum[6]; v1.w = acc[i][7] + bsum[7];
        *(float4*)(C + (size_t)(row0 + i) * N + col0)     = v0;
        *(float4*)(C + (size_t)(row0 + i) * N + col0 + 4) = v1;
    }
}

// ---------------------------------------------------------------------------
// LSTM cell elementwise: gates [B,4H] -> h,c update. torch gate order i,f,g,o.
// ---------------------------------------------------------------------------
__global__ void cell_kernel() {
    int idx = blockIdx.x * blockDim.x + threadIdx.x;  // 0 .. B*H-1
    int b = idx >> 10;        // H = 1024
    int hh = idx & 1023;
    const float* gr = g_gates + (size_t)b * GG;
    float gi = gr[hh];
    float gf = gr[HH + hh];
    float gg = gr[2 * HH + hh];
    float go = gr[3 * HH + hh];
    gi = 1.0f / (1.0f + expf(-gi));
    gf = 1.0f / (1.0f + expf(-gf));
    go = 1.0f / (1.0f + expf(-go));
    gg = tanhf(gg);
    float c = gf * g_c[idx] + gi * gg;
    g_c[idx] = c;
    g_h[idx] = go * tanhf(c);
}

// ---------------------------------------------------------------------------
extern "C" void kernel_launch(void* const* d_in, const int* in_sizes, int n_in,
                              void* d_out, int out_size) {
    const int*   m     = (const int*)d_in[0];
    const float* tab   = (const float*)d_in[1];
    const float* W_ih  = (const float*)d_in[2];
    const float* W_hh  = (const float*)d_in[3];
    const float* b_ih  = (const float*)d_in[4];
    const float* b_hh  = (const float*)d_in[5];
    const float* W_out = (const float*)d_in[6];
    const float* b_out = (const float*)d_in[7];
    float* out = (float*)d_out;

    float *embs, *gates, *h, *zero;
    cudaGetSymbolAddress((void**)&embs,  g_embs);
    cudaGetSymbolAddress((void**)&gates, g_gates);
    cudaGetSymbolAddress((void**)&h,     g_h);
    cudaGetSymbolAddress((void**)&zero,  g_zero);

    // 1) embedding gather (time-major)
    gather_kernel<<<SS * BB, 128>>>(m, tab);

    // 2) zero initial state
    zero_hc_kernel<<<(BB * HH) / 256, 256>>>();

    // 3) recurrence: gates = [emb_s | h] @ [W_ih | W_hh]^T + b_ih + b_hh, then cell
    dim3 ggrid(NN / 128, BB / 128);   // (32, 8)
    for (int s = 0; s < SS; s++) {
        const float* embS = embs + (size_t)s * BB * EE;
        gemm_nt<true><<<ggrid, 256>>>(
            embS, EE, h, HH,
            W_ih, EE, W_hh, HH,
            EE, EE + HH,
            b_ih, b_hh,
            gates, GG);
        cell_kernel<<<(BB * HH) / 256, 256>>>();
    }

    // 4) output projection: out = h @ W_out^T + b_out
    gemm_nt<false><<<ggrid, 256>>>(
        h, HH, nullptr, 0,
        W_out, HH, nullptr, 0,
        HH, HH,
        b_out, zero,
        out, NN);
}

// round 9
// speedup vs baseline: 1.2640x; 1.2640x over previous
#include <cuda_runtime.h>
#include <cstdint>
#include <math.h>

// Problem dims (fixed)
#define BB 1024   // batch
#define SS 128    // seq len
#define VV 20000  // vocab
#define EE 512    // embed dim
#define HH 1024   // hidden
#define GG 4096   // 4*H (gates)
#define KTOT 1536 // E + H
#define NN 4096   // output dim

// Tiling
#define BM 128
#define BN 128
#define BK 32
#define NST 3
#define LDS_F 36                         // smem row stride in floats
#define ASZ (BM * LDS_F * 4)             // 18432 B (one A tile, hi OR lo)
#define BSZ (BN * LDS_F * 4)             // 18432 B
#define STAGE (2*ASZ + 2*BSZ)            // 73728 B (hi+lo for A and B)
#define SMEM_TOTAL (NST * STAGE)         // 221184 B

// Scratch (split hi/lo representations)
__device__ float g_tabh[(size_t)VV * EE];
__device__ float g_tabl[(size_t)VV * EE];
__device__ float g_wph[(size_t)GG * KTOT];
__device__ float g_wpl[(size_t)GG * KTOT];
__device__ float g_woh[(size_t)NN * HH];
__device__ float g_wol[(size_t)NN * HH];
__device__ float g_biasp[GG];
__device__ float g_hhiA[BB * HH];        // h ping-pong buffers (race fix)
__device__ float g_hhiB[BB * HH];
__device__ float g_hloA[BB * HH];
__device__ float g_hloB[BB * HH];
__device__ float g_c[BB * HH];

// ---------------------------------------------------------------------------
__device__ __forceinline__ uint32_t smem_u32(const void* p) {
    uint32_t a;
    asm("{ .reg .u64 t; cvta.to.shared.u64 t, %1; cvt.u32.u64 %0, t; }" : "=r"(a) : "l"(p));
    return a;
}
#define CP16(dst, src) \
    asm volatile("cp.async.cg.shared.global [%0], [%1], 16;" :: "r"(dst), "l"(src))
#define CP_COMMIT() asm volatile("cp.async.commit_group;" ::: "memory")
#define CP_WAIT2()  asm volatile("cp.async.wait_group 2;" ::: "memory")

__device__ __forceinline__ void ldsm4(uint32_t& r0, uint32_t& r1, uint32_t& r2,
                                      uint32_t& r3, uint32_t addr) {
    asm volatile("ldmatrix.sync.aligned.m8n8.x4.shared.b16 {%0,%1,%2,%3}, [%4];"
                 : "=r"(r0), "=r"(r1), "=r"(r2), "=r"(r3) : "r"(addr));
}
__device__ __forceinline__ void ldsm2(uint32_t& r0, uint32_t& r1, uint32_t addr) {
    asm volatile("ldmatrix.sync.aligned.m8n8.x2.shared.b16 {%0,%1}, [%2];"
                 : "=r"(r0), "=r"(r1) : "r"(addr));
}
__device__ __forceinline__ void mma_tf32(float* c, const uint32_t* a, const uint32_t* b) {
    asm volatile(
        "mma.sync.aligned.m16n8k8.row.col.f32.tf32.tf32.f32 "
        "{%0,%1,%2,%3}, {%4,%5,%6,%7}, {%8,%9}, {%0,%1,%2,%3};"
        : "+f"(c[0]), "+f"(c[1]), "+f"(c[2]), "+f"(c[3])
        : "r"(a[0]), "r"(a[1]), "r"(a[2]), "r"(a[3]), "r"(b[0]), "r"(b[1]));
}
__device__ __forceinline__ float fsigmoid(float x) { return 1.0f / (1.0f + expf(-x)); }

// split x into tf32 hi + tf32 lo
__device__ __forceinline__ float2 tf32split(float x) {
    uint32_t hb;
    asm("cvt.rna.tf32.f32 %0, %1;" : "=r"(hb) : "f"(x));
    float hi = __uint_as_float(hb);
    float r = x - hi;
    uint32_t lb;
    asm("cvt.rna.tf32.f32 %0, %1;" : "=r"(lb) : "f"(r));
    float2 o; o.x = hi; o.y = __uint_as_float(lb);
    return o;
}
__device__ __forceinline__ void split4(float4 v, float4& h, float4& l) {
    float2 a = tf32split(v.x), b = tf32split(v.y), c = tf32split(v.z), d = tf32split(v.w);
    h.x = a.x; h.y = b.x; h.z = c.x; h.w = d.x;
    l.x = a.y; l.y = b.y; l.z = c.y; l.w = d.y;
}

// ---------------------------------------------------------------------------
// Prep kernels
// ---------------------------------------------------------------------------
__global__ void splitTab_kernel(const float* __restrict__ tab) {
    int v = blockIdx.x;
    const float4* s = (const float4*)(tab + (size_t)v * EE);
    float4* dh = (float4*)(g_tabh + (size_t)v * EE);
    float4* dl = (float4*)(g_tabl + (size_t)v * EE);
    float4 h, l;
    split4(s[threadIdx.x], h, l);
    dh[threadIdx.x] = h; dl[threadIdx.x] = l;
}
__global__ void zero_hc_kernel() {
    int i = blockIdx.x * blockDim.x + threadIdx.x;
    g_hhiA[i] = 0.0f; g_hhiB[i] = 0.0f;
    g_hloA[i] = 0.0f; g_hloB[i] = 0.0f;
    g_c[i] = 0.0f;
}
// Wp[4u+g, :] = [W_ih[g*H+u, :] | W_hh[g*H+u, :]], split hi/lo
__global__ void permW_kernel(const float* __restrict__ Wih, const float* __restrict__ Whh) {
    int n = blockIdx.x;
    int u = n >> 2, g = n & 3;
    int sr = g * HH + u;
    float4* dh = (float4*)(g_wph + (size_t)n * KTOT);
    float4* dl = (float4*)(g_wpl + (size_t)n * KTOT);
    const float4* s1 = (const float4*)(Wih + (size_t)sr * EE);
    const float4* s2 = (const float4*)(Whh + (size_t)sr * HH);
    float4 h, l;
    split4(s1[threadIdx.x], h, l);           dh[threadIdx.x] = h;       dl[threadIdx.x] = l;
    split4(s2[threadIdx.x], h, l);           dh[128 + threadIdx.x] = h; dl[128 + threadIdx.x] = l;
    split4(s2[128 + threadIdx.x], h, l);     dh[256 + threadIdx.x] = h; dl[256 + threadIdx.x] = l;
}
__global__ void permB_kernel(const float* __restrict__ bih, const float* __restrict__ bhh) {
    int n = blockIdx.x * blockDim.x + threadIdx.x;
    int u = n >> 2, g = n & 3;
    int sr = g * HH + u;
    g_biasp[n] = bih[sr] + bhh[sr];
}
__global__ void splitWout_kernel(const float* __restrict__ Wout) {
    int n = blockIdx.x;
    const float4* s = (const float4*)(Wout + (size_t)n * HH);
    float4* dh = (float4*)(g_woh + (size_t)n * HH);
    float4* dl = (float4*)(g_wol + (size_t)n * HH);
    float4 h, l;
    split4(s[threadIdx.x], h, l);        dh[threadIdx.x] = h;        dl[threadIdx.x] = l;
    split4(s[128 + threadIdx.x], h, l);  dh[128 + threadIdx.x] = h;  dl[128 + threadIdx.x] = l;
}

// ---------------------------------------------------------------------------
// 3xTF32 mma.sync GEMM: C = A*B^T with A,B given as (hi,lo) tf32 pairs.
// CELL=true: A = [emb(m[b,s]) | hIn] (gather fused), LSTM epilogue -> hOut, c.
//            hIn/hOut are DISTINCT buffers (ping-pong) to avoid the intra-launch
//            RAW race (other blocks read all of h while this block writes its slice).
// CELL=false: A = (A1h,A1l), plain bias+store epilogue.
// ---------------------------------------------------------------------------
template <bool CELL>
__global__ __launch_bounds__(256, 1) void lstm_gemm(
    const int* __restrict__ mPtr, int sStep,
    const float* __restrict__ tabh, const float* __restrict__ tabl,
    const float* __restrict__ A1h, const float* __restrict__ A1l, int lda,
    const float* __restrict__ Bh,  const float* __restrict__ Bl,  int ldb,
    int nIter,
    const float* __restrict__ bias,
    const float* __restrict__ hInHi, const float* __restrict__ hInLo,
    float* __restrict__ hOutHi, float* __restrict__ hOutLo,
    float* __restrict__ cPtr,
    float* __restrict__ out)
{
    extern __shared__ __align__(16) char smem[];
    __shared__ int msm[BM];
    const uint32_t sb = smem_u32(smem);
    const int tid  = threadIdx.x;
    const int wid  = tid >> 5, lane = tid & 31;
    const int wm   = wid >> 2;            // 0..1
    const int wn   = wid & 3;             // 0..3
    const int row0 = blockIdx.y * BM;
    const int col0 = blockIdx.x * BN;

    if (CELL) {
        if (tid < BM) msm[tid] = mPtr[(size_t)(row0 + tid) * SS + sStep];
        __syncthreads();
    }

    float acc[4][4][4];
#pragma unroll
    for (int i = 0; i < 4; i++)
#pragma unroll
        for (int j = 0; j < 4; j++)
#pragma unroll
            for (int r = 0; r < 4; r++) acc[i][j][r] = 0.0f;

    // stage layout: [Ah | Al | Bh | Bl]
    auto load_stage = [&](int slot, int k0) {
        const uint32_t ah = sb + slot * STAGE;
        const uint32_t al = ah + ASZ;
        const uint32_t bh = al + ASZ;
        const uint32_t bl = bh + BSZ;
#pragma unroll
        for (int j = 0; j < 4; j++) {
            int cidx = tid + j * 256;      // 0..1023
            int r = cidx >> 3, q = cidx & 7;
            uint32_t soff = (uint32_t)(r * LDS_F + q * 4) * 4;
            if (CELL) {
                if (k0 < EE) {             // embedding columns: gather from table
                    size_t goff = (size_t)msm[r] * EE + k0 + q * 4;
                    CP16(ah + soff, tabh + goff);
                    CP16(al + soff, tabl + goff);
                } else {                   // hidden columns (previous step's h)
                    size_t goff = (size_t)(row0 + r) * HH + (k0 - EE) + q * 4;
                    CP16(ah + soff, hInHi + goff);
                    CP16(al + soff, hInLo + goff);
                }
            } else {
                size_t goff = (size_t)(row0 + r) * lda + k0 + q * 4;
                CP16(ah + soff, A1h + goff);
                CP16(al + soff, A1l + goff);
            }
        }
#pragma unroll
        for (int j = 0; j < 4; j++) {
            int cidx = tid + j * 256;
            int r = cidx >> 3, q = cidx & 7;
            uint32_t soff = (uint32_t)(r * LDS_F + q * 4) * 4;
            size_t goff = (size_t)(col0 + r) * ldb + k0 + q * 4;
            CP16(bh + soff, Bh + goff);
            CP16(bl + soff, Bl + goff);
        }
    };

    auto compute = [&](int slot) {
        const uint32_t ah = sb + slot * STAGE;
        const uint32_t al = ah + ASZ;
        const uint32_t bh = al + ASZ;
        const uint32_t bl = bh + BSZ;
        const int arow = wm * 64 + (lane & 15);
        const int acol = (lane >> 4) * 4;
        const int brow = wn * 32 + (lane & 7);
        const int bcol = ((lane >> 3) & 1) * 4;
#pragma unroll
        for (int ks = 0; ks < 4; ks++) {
            const int k0 = ks * 8;
            uint32_t afh[4][4], afl[4][4], bfh[4][2], bfl[4][2];
#pragma unroll
            for (int mt = 0; mt < 4; mt++) {
                uint32_t off = (uint32_t)((arow + mt * 16) * LDS_F + acol + k0) * 4;
                ldsm4(afh[mt][0], afh[mt][1], afh[mt][2], afh[mt][3], ah + off);
                ldsm4(afl[mt][0], afl[mt][1], afl[mt][2], afl[mt][3], al + off);
            }
#pragma unroll
            for (int nt = 0; nt < 4; nt++) {
                uint32_t off = (uint32_t)((brow + nt * 8) * LDS_F + bcol + k0) * 4;
                ldsm2(bfh[nt][0], bfh[nt][1], bh + off);
                ldsm2(bfl[nt][0], bfl[nt][1], bl + off);
            }
#pragma unroll
            for (int mt = 0; mt < 4; mt++)
#pragma unroll
                for (int nt = 0; nt < 4; nt++) {
                    mma_tf32(acc[mt][nt], afh[mt], bfh[nt]);   // hi*hi
                    mma_tf32(acc[mt][nt], afl[mt], bfh[nt]);   // lo*hi
                    mma_tf32(acc[mt][nt], afh[mt], bfl[nt]);   // hi*lo
                }
        }
    };

    load_stage(0, 0); CP_COMMIT();
    if (nIter > 1) load_stage(1, BK);
    CP_COMMIT();
    for (int it = 0; it < nIter; ++it) {
        if (it + 2 < nIter) load_stage((it + 2) % NST, (it + 2) * BK);
        CP_COMMIT();
        CP_WAIT2();
        __syncthreads();
        compute(it % NST);
        __syncthreads();
    }

    if (CELL) {
        float* gsm = (float*)smem;                 // [64][132]
        const int h0 = col0 >> 2;
#pragma unroll
        for (int half = 0; half < 2; half++) {
            __syncthreads();
            if (wm == half) {
#pragma unroll
                for (int mt = 0; mt < 4; mt++) {
                    const int lr = mt * 16 + (lane >> 2);
#pragma unroll
                    for (int nt = 0; nt < 4; nt++) {
                        const int cc = wn * 32 + nt * 8 + 2 * (lane & 3);
                        float2 v0 = {acc[mt][nt][0], acc[mt][nt][1]};
                        float2 v1 = {acc[mt][nt][2], acc[mt][nt][3]};
                        *(float2*)&gsm[lr * 132 + cc]       = v0;
                        *(float2*)&gsm[(lr + 8) * 132 + cc] = v1;
                    }
                }
            }
            __syncthreads();
#pragma unroll
            for (int j = 0; j < 8; j++) {
                const int idx = tid + j * 256;     // 0..2047
                const int lr = idx >> 5, u = idx & 31;
                const float4 g  = *(const float4*)&gsm[lr * 132 + 4 * u];
                const float4 bv = *(const float4*)&bias[col0 + 4 * u];
                const int grow = row0 + half * 64 + lr;
                const size_t off = (size_t)grow * HH + h0 + u;
                const float co = cPtr[off];
                const float gi = fsigmoid(g.x + bv.x);
                const float gf = fsigmoid(g.y + bv.y);
                const float gg = tanhf(g.z + bv.z);
                const float go = fsigmoid(g.w + bv.w);
                const float cn = gf * co + gi * gg;
                const float hn = go * tanhf(cn);
                cPtr[off] = cn;
                float2 sp = tf32split(hn);
                hOutHi[off] = sp.x;
                hOutLo[off] = sp.y;
            }
        }
    } else {
#pragma unroll
        for (int mt = 0; mt < 4; mt++) {
            const int rr = row0 + wm * 64 + mt * 16 + (lane >> 2);
#pragma unroll
            for (int nt = 0; nt < 4; nt++) {
                const int cc = col0 + wn * 32 + nt * 8 + 2 * (lane & 3);
                float2 v0 = {acc[mt][nt][0] + bias[cc], acc[mt][nt][1] + bias[cc + 1]};
                float2 v1 = {acc[mt][nt][2] + bias[cc], acc[mt][nt][3] + bias[cc + 1]};
                *(float2*)(out + (size_t)rr * NN + cc)       = v0;
                *(float2*)(out + (size_t)(rr + 8) * NN + cc) = v1;
            }
        }
    }
}

// ---------------------------------------------------------------------------
extern "C" void kernel_launch(void* const* d_in, const int* in_sizes, int n_in,
                              void* d_out, int out_size) {
    const int*   m     = (const int*)d_in[0];
    const float* tab   = (const float*)d_in[1];
    const float* W_ih  = (const float*)d_in[2];
    const float* W_hh  = (const float*)d_in[3];
    const float* b_ih  = (const float*)d_in[4];
    const float* b_hh  = (const float*)d_in[5];
    const float* W_out = (const float*)d_in[6];
    const float* b_out = (const float*)d_in[7];
    float* out = (float*)d_out;

    float *tabh, *tabl, *wph, *wpl, *woh, *wol, *biasp, *c;
    float *hhi[2], *hlo[2];
    cudaGetSymbolAddress((void**)&tabh,    g_tabh);
    cudaGetSymbolAddress((void**)&tabl,    g_tabl);
    cudaGetSymbolAddress((void**)&wph,     g_wph);
    cudaGetSymbolAddress((void**)&wpl,     g_wpl);
    cudaGetSymbolAddress((void**)&woh,     g_woh);
    cudaGetSymbolAddress((void**)&wol,     g_wol);
    cudaGetSymbolAddress((void**)&biasp,   g_biasp);
    cudaGetSymbolAddress((void**)&hhi[0],  g_hhiA);
    cudaGetSymbolAddress((void**)&hhi[1],  g_hhiB);
    cudaGetSymbolAddress((void**)&hlo[0],  g_hloA);
    cudaGetSymbolAddress((void**)&hlo[1],  g_hloB);
    cudaGetSymbolAddress((void**)&c,       g_c);

    cudaFuncSetAttribute(lstm_gemm<true>,  cudaFuncAttributeMaxDynamicSharedMemorySize, SMEM_TOTAL);
    cudaFuncSetAttribute(lstm_gemm<false>, cudaFuncAttributeMaxDynamicSharedMemorySize, SMEM_TOTAL);

    splitTab_kernel<<<VV, 128>>>(tab);
    zero_hc_kernel<<<(BB * HH) / 256, 256>>>();
    permW_kernel<<<GG, 128>>>(W_ih, W_hh);
    permB_kernel<<<GG / 256, 256>>>(b_ih, b_hh);
    splitWout_kernel<<<NN, 128>>>(W_out);

    dim3 grid(NN / BN, BB / BM);   // (32, 8)
    for (int s = 0; s < SS; s++) {
        const int rd = s & 1, wr = (s + 1) & 1;   // ping-pong h (race fix)
        lstm_gemm<true><<<grid, 256, SMEM_TOTAL>>>(
            m, s, tabh, tabl,
            nullptr, nullptr, 0,
            wph, wpl, KTOT,
            KTOT / BK,              // 48 iters
            biasp,
            hhi[rd], hlo[rd],       // read h_s
            hhi[wr], hlo[wr],       // write h_{s+1}
            c, nullptr);
    }
    // after 128 steps, final h is in buffer (SS & 1) = 0
    lstm_gemm<false><<<grid, 256, SMEM_TOTAL>>>(
        nullptr, 0, nullptr, nullptr,
        hhi[0], hlo[0], HH,
        woh, wol, HH,
        HH / BK,                    // 32 iters
        b_out,
        nullptr, nullptr, nullptr, nullptr, nullptr, out);
}

// round 12
// speedup vs baseline: 2.4450x; 1.9343x over previous
#include <cuda_runtime.h>
#include <cuda_bf16.h>
#include <cstdint>
#include <math.h>

// Problem dims (fixed)
#define BB 1024   // batch
#define SS 128    // seq len
#define VV 20000  // vocab
#define EE 512    // embed dim
#define HH 1024   // hidden
#define GG 4096   // 4*H (gates)
#define KTOT 1536 // E + H
#define NN 4096   // output dim

// Tiling (bf16: BK=64 elems per stage, mma.m16n8k16)
#define BM 128
#define BN 128
#define BK 64
#define NST 3
#define ROWB 144                          // bytes per smem tile row (128 data + 16 pad)
#define TILEB (128 * ROWB)                // 18432 B
#define STAGE (4 * TILEB)                 // Ah|Al|Bh|Bl = 73728 B
#define SMEM_TOTAL (NST * STAGE)          // 221184 B

typedef __nv_bfloat16 bf16;

// Scratch: everything pre-split into bf16 (hi, lo) pairs
__device__ bf16 g_tabh[(size_t)VV * EE];
__device__ bf16 g_tabl[(size_t)VV * EE];
__device__ bf16 g_wph[(size_t)GG * KTOT];
__device__ bf16 g_wpl[(size_t)GG * KTOT];
__device__ bf16 g_woh[(size_t)NN * HH];
__device__ bf16 g_wol[(size_t)NN * HH];
__device__ float g_biasp[GG];
__device__ bf16 g_hhiA[BB * HH];          // h ping-pong (intra-launch race fix)
__device__ bf16 g_hhiB[BB * HH];
__device__ bf16 g_hloA[BB * HH];
__device__ bf16 g_hloB[BB * HH];
__device__ float g_c[BB * HH];

// ---------------------------------------------------------------------------
__device__ __forceinline__ uint32_t smem_u32(const void* p) {
    uint32_t a;
    asm("{ .reg .u64 t; cvta.to.shared.u64 t, %1; cvt.u32.u64 %0, t; }" : "=r"(a) : "l"(p));
    return a;
}
#define CP16(dst, src) \
    asm volatile("cp.async.cg.shared.global [%0], [%1], 16;" :: "r"(dst), "l"(src))
#define CP_COMMIT() asm volatile("cp.async.commit_group;" ::: "memory")
#define CP_WAIT2()  asm volatile("cp.async.wait_group 2;" ::: "memory")

__device__ __forceinline__ void ldsm4(uint32_t& r0, uint32_t& r1, uint32_t& r2,
                                      uint32_t& r3, uint32_t addr) {
    asm volatile("ldmatrix.sync.aligned.m8n8.x4.shared.b16 {%0,%1,%2,%3}, [%4];"
                 : "=r"(r0), "=r"(r1), "=r"(r2), "=r"(r3) : "r"(addr));
}
__device__ __forceinline__ void ldsm2(uint32_t& r0, uint32_t& r1, uint32_t addr) {
    asm volatile("ldmatrix.sync.aligned.m8n8.x2.shared.b16 {%0,%1}, [%2];"
                 : "=r"(r0), "=r"(r1) : "r"(addr));
}
__device__ __forceinline__ void mma_bf16(float* c, const uint32_t* a, const uint32_t* b) {
    asm volatile(
        "mma.sync.aligned.m16n8k16.row.col.f32.bf16.bf16.f32 "
        "{%0,%1,%2,%3}, {%4,%5,%6,%7}, {%8,%9}, {%0,%1,%2,%3};"
        : "+f"(c[0]), "+f"(c[1]), "+f"(c[2]), "+f"(c[3])
        : "r"(a[0]), "r"(a[1]), "r"(a[2]), "r"(a[3]), "r"(b[0]), "r"(b[1]));
}
__device__ __forceinline__ float fsigmoid(float x) { return 1.0f / (1.0f + expf(-x)); }

// split x into bf16 hi + bf16 lo (≈16 mantissa bits total)
__device__ __forceinline__ void bsplit(float x, bf16& h, bf16& l) {
    h = __float2bfloat16(x);
    l = __float2bfloat16(x - __bfloat162float(h));
}

// ---------------------------------------------------------------------------
// Prep kernels
// ---------------------------------------------------------------------------
__global__ void splitTab_kernel(const float* __restrict__ tab) {
    int v = blockIdx.x;
    const float4* s = (const float4*)(tab + (size_t)v * EE);
    float4 val = s[threadIdx.x];
    size_t d = (size_t)v * EE + threadIdx.x * 4;
    bsplit(val.x, g_tabh[d + 0], g_tabl[d + 0]);
    bsplit(val.y, g_tabh[d + 1], g_tabl[d + 1]);
    bsplit(val.z, g_tabh[d + 2], g_tabl[d + 2]);
    bsplit(val.w, g_tabh[d + 3], g_tabl[d + 3]);
}
__global__ void zero_hc_kernel() {
    int i = blockIdx.x * blockDim.x + threadIdx.x;
    bf16 z = __float2bfloat16(0.0f);
    g_hhiA[i] = z; g_hhiB[i] = z; g_hloA[i] = z; g_hloB[i] = z;
    g_c[i] = 0.0f;
}
// Wp[4u+g, :] = [W_ih[g*H+u, :] | W_hh[g*H+u, :]], split bf16 hi/lo
__global__ void permW_kernel(const float* __restrict__ Wih, const float* __restrict__ Whh) {
    int n = blockIdx.x;
    int u = n >> 2, g = n & 3;
    int sr = g * HH + u;
    const float4* s1 = (const float4*)(Wih + (size_t)sr * EE);
    const float4* s2 = (const float4*)(Whh + (size_t)sr * HH);
    size_t base = (size_t)n * KTOT;
    float4 v;
    v = s1[threadIdx.x];
    {   size_t d = base + threadIdx.x * 4;
        bsplit(v.x, g_wph[d+0], g_wpl[d+0]); bsplit(v.y, g_wph[d+1], g_wpl[d+1]);
        bsplit(v.z, g_wph[d+2], g_wpl[d+2]); bsplit(v.w, g_wph[d+3], g_wpl[d+3]); }
    v = s2[threadIdx.x];
    {   size_t d = base + EE + threadIdx.x * 4;
        bsplit(v.x, g_wph[d+0], g_wpl[d+0]); bsplit(v.y, g_wph[d+1], g_wpl[d+1]);
        bsplit(v.z, g_wph[d+2], g_wpl[d+2]); bsplit(v.w, g_wph[d+3], g_wpl[d+3]); }
    v = s2[128 + threadIdx.x];
    {   size_t d = base + EE + 512 + threadIdx.x * 4;
        bsplit(v.x, g_wph[d+0], g_wpl[d+0]); bsplit(v.y, g_wph[d+1], g_wpl[d+1]);
        bsplit(v.z, g_wph[d+2], g_wpl[d+2]); bsplit(v.w, g_wph[d+3], g_wpl[d+3]); }
}
__global__ void permB_kernel(const float* __restrict__ bih, const float* __restrict__ bhh) {
    int n = blockIdx.x * blockDim.x + threadIdx.x;
    int u = n >> 2, g = n & 3;
    int sr = g * HH + u;
    g_biasp[n] = bih[sr] + bhh[sr];
}
__global__ void splitWout_kernel(const float* __restrict__ Wout) {
    int n = blockIdx.x;
    const float4* s = (const float4*)(Wout + (size_t)n * HH);
    size_t base = (size_t)n * HH;
#pragma unroll
    for (int seg = 0; seg < 2; seg++) {
        float4 v = s[seg * 128 + threadIdx.x];
        size_t d = base + (seg * 128 + threadIdx.x) * 4;
        bsplit(v.x, g_woh[d+0], g_wol[d+0]); bsplit(v.y, g_woh[d+1], g_wol[d+1]);
        bsplit(v.z, g_woh[d+2], g_wol[d+2]); bsplit(v.w, g_woh[d+3], g_wol[d+3]);
    }
}

// ---------------------------------------------------------------------------
// bf16x3 mma.sync GEMM: C = A*B^T with A,B as (hi,lo) bf16 pairs.
// CELL=true: A = [emb(m[b,s]) | hIn] (gather fused), LSTM epilogue -> hOut, c.
//            ping-pong h buffers (race fix). CELL=false: plain bias+store.
// ---------------------------------------------------------------------------
template <bool CELL>
__global__ __launch_bounds__(256, 1) void lstm_gemm(
    const int* __restrict__ mPtr, int sStep,
    const bf16* __restrict__ tabh, const bf16* __restrict__ tabl,
    const bf16* __restrict__ A1h, const bf16* __restrict__ A1l, int lda,
    const bf16* __restrict__ Bh,  const bf16* __restrict__ Bl,  int ldb,
    int nIter,
    const float* __restrict__ bias,
    const bf16* __restrict__ hInHi, const bf16* __restrict__ hInLo,
    bf16* __restrict__ hOutHi, bf16* __restrict__ hOutLo,
    float* __restrict__ cPtr,
    float* __restrict__ out)
{
    extern __shared__ __align__(16) char smem[];
    __shared__ int msm[BM];
    const uint32_t sb = smem_u32(smem);
    const int tid  = threadIdx.x;
    const int wid  = tid >> 5, lane = tid & 31;
    const int wm   = wid >> 2;            // 0..1
    const int wn   = wid & 3;             // 0..3
    const int row0 = blockIdx.y * BM;
    const int col0 = blockIdx.x * BN;

    if (CELL) {
        if (tid < BM) msm[tid] = mPtr[(size_t)(row0 + tid) * SS + sStep];
        __syncthreads();
    }

    float acc[4][4][4];
#pragma unroll
    for (int i = 0; i < 4; i++)
#pragma unroll
        for (int j = 0; j < 4; j++)
#pragma unroll
            for (int r = 0; r < 4; r++) acc[i][j][r] = 0.0f;

    // stage layout: [Ah | Al | Bh | Bl], each 128 rows x 144B (64 bf16 + pad)
    auto load_stage = [&](int slot, int k0) {
        const uint32_t ah = sb + slot * STAGE;
        const uint32_t al = ah + TILEB;
        const uint32_t bh = al + TILEB;
        const uint32_t bl = bh + TILEB;
#pragma unroll
        for (int j = 0; j < 4; j++) {
            int cidx = tid + j * 256;      // 0..1023 : 128 rows x 8 chunks
            int r = cidx >> 3, q = cidx & 7;
            uint32_t soff = (uint32_t)(r * ROWB + q * 16);
            if (CELL) {
                if (k0 < EE) {             // embedding columns: gather from table
                    size_t goff = (size_t)msm[r] * EE + k0 + q * 8;
                    CP16(ah + soff, tabh + goff);
                    CP16(al + soff, tabl + goff);
                } else {                   // hidden columns (previous step's h)
                    size_t goff = (size_t)(row0 + r) * HH + (k0 - EE) + q * 8;
                    CP16(ah + soff, hInHi + goff);
                    CP16(al + soff, hInLo + goff);
                }
            } else {
                size_t goff = (size_t)(row0 + r) * lda + k0 + q * 8;
                CP16(ah + soff, A1h + goff);
                CP16(al + soff, A1l + goff);
            }
        }
#pragma unroll
        for (int j = 0; j < 4; j++) {
            int cidx = tid + j * 256;
            int r = cidx >> 3, q = cidx & 7;
            uint32_t soff = (uint32_t)(r * ROWB + q * 16);
            size_t goff = (size_t)(col0 + r) * ldb + k0 + q * 8;
            CP16(bh + soff, Bh + goff);
            CP16(bl + soff, Bl + goff);
        }
    };

    auto compute = [&](int slot) {
        const uint32_t ah = sb + slot * STAGE;
        const uint32_t al = ah + TILEB;
        const uint32_t bh = al + TILEB;
        const uint32_t bl = bh + TILEB;
        const int arow  = wm * 64 + (lane & 15);
        const int acolB = (lane >> 4) * 16;          // byte offset of k-half
        const int brow  = wn * 32 + (lane & 7);
        const int bcolB = ((lane >> 3) & 1) * 16;
#pragma unroll
        for (int ks = 0; ks < 4; ks++) {             // 4 x k16 per BK=64 stage
            const int kB = ks * 32;                  // 16 bf16 = 32 bytes
            uint32_t afh[4][4], afl[4][4], bfh[4][2], bfl[4][2];
#pragma unroll
            for (int mt = 0; mt < 4; mt++) {
                uint32_t off = (uint32_t)((arow + mt * 16) * ROWB + acolB + kB);
                ldsm4(afh[mt][0], afh[mt][1], afh[mt][2], afh[mt][3], ah + off);
                ldsm4(afl[mt][0], afl[mt][1], afl[mt][2], afl[mt][3], al + off);
            }
#pragma unroll
            for (int nt = 0; nt < 4; nt++) {
                uint32_t off = (uint32_t)((brow + nt * 8) * ROWB + bcolB + kB);
                ldsm2(bfh[nt][0], bfh[nt][1], bh + off);
                ldsm2(bfl[nt][0], bfl[nt][1], bl + off);
            }
#pragma unroll
            for (int mt = 0; mt < 4; mt++)
#pragma unroll
                for (int nt = 0; nt < 4; nt++) {
                    mma_bf16(acc[mt][nt], afh[mt], bfh[nt]);   // hi*hi
                    mma_bf16(acc[mt][nt], afl[mt], bfh[nt]);   // lo*hi
                    mma_bf16(acc[mt][nt], afh[mt], bfl[nt]);   // hi*lo
                }
        }
    };

    load_stage(0, 0); CP_COMMIT();
    if (nIter > 1) load_stage(1, BK);
    CP_COMMIT();
    for (int it = 0; it < nIter; ++it) {
        if (it + 2 < nIter) load_stage((it + 2) % NST, (it + 2) * BK);
        CP_COMMIT();
        CP_WAIT2();
        __syncthreads();
        compute(it % NST);
        __syncthreads();
    }

    if (CELL) {
        float* gsm = (float*)smem;                 // [64][132] staging
        const int h0 = col0 >> 2;
#pragma unroll
        for (int half = 0; half < 2; half++) {
            __syncthreads();
            if (wm == half) {
#pragma unroll
                for (int mt = 0; mt < 4; mt++) {
                    const int lr = mt * 16 + (lane >> 2);
#pragma unroll
                    for (int nt = 0; nt < 4; nt++) {
                        const int cc = wn * 32 + nt * 8 + 2 * (lane & 3);
                        float2 v0 = {acc[mt][nt][0], acc[mt][nt][1]};
                        float2 v1 = {acc[mt][nt][2], acc[mt][nt][3]};
                        *(float2*)&gsm[lr * 132 + cc]       = v0;
                        *(float2*)&gsm[(lr + 8) * 132 + cc] = v1;
                    }
                }
            }
            __syncthreads();
#pragma unroll
            for (int j = 0; j < 8; j++) {
                const int idx = tid + j * 256;     // 0..2047
                const int lr = idx >> 5, u = idx & 31;
                const float4 g  = *(const float4*)&gsm[lr * 132 + 4 * u];
                const float4 bv = *(const float4*)&bias[col0 + 4 * u];
                const int grow = row0 + half * 64 + lr;
                const size_t off = (size_t)grow * HH + h0 + u;
                const float co = cPtr[off];
                const float gi = fsigmoid(g.x + bv.x);
                const float gf = fsigmoid(g.y + bv.y);
                const float gg = tanhf(g.z + bv.z);
                const float go = fsigmoid(g.w + bv.w);
                const float cn = gf * co + gi * gg;
                const float hn = go * tanhf(cn);
                cPtr[off] = cn;
                bf16 hb = __float2bfloat16(hn);
                hOutHi[off] = hb;
                hOutLo[off] = __float2bfloat16(hn - __bfloat162float(hb));
            }
        }
    } else {
#pragma unroll
        for (int mt = 0; mt < 4; mt++) {
            const int rr = row0 + wm * 64 + mt * 16 + (lane >> 2);
#pragma unroll
            for (int nt = 0; nt < 4; nt++) {
                const int cc = col0 + wn * 32 + nt * 8 + 2 * (lane & 3);
                float2 v0 = {acc[mt][nt][0] + bias[cc], acc[mt][nt][1] + bias[cc + 1]};
                float2 v1 = {acc[mt][nt][2] + bias[cc], acc[mt][nt][3] + bias[cc + 1]};
                *(float2*)(out + (size_t)rr * NN + cc)       = v0;
                *(float2*)(out + (size_t)(rr + 8) * NN + cc) = v1;
            }
        }
    }
}

// ---------------------------------------------------------------------------
extern "C" void kernel_launch(void* const* d_in, const int* in_sizes, int n_in,
                              void* d_out, int out_size) {
    const int*   m     = (const int*)d_in[0];
    const float* tab   = (const float*)d_in[1];
    const float* W_ih  = (const float*)d_in[2];
    const float* W_hh  = (const float*)d_in[3];
    const float* b_ih  = (const float*)d_in[4];
    const float* b_hh  = (const float*)d_in[5];
    const float* W_out = (const float*)d_in[6];
    const float* b_out = (const float*)d_in[7];
    float* out = (float*)d_out;

    bf16 *tabh, *tabl, *wph, *wpl, *woh, *wol;
    float *biasp, *c;
    bf16 *hhi[2], *hlo[2];
    cudaGetSymbolAddress((void**)&tabh,    g_tabh);
    cudaGetSymbolAddress((void**)&tabl,    g_tabl);
    cudaGetSymbolAddress((void**)&wph,     g_wph);
    cudaGetSymbolAddress((void**)&wpl,     g_wpl);
    cudaGetSymbolAddress((void**)&woh,     g_woh);
    cudaGetSymbolAddress((void**)&wol,     g_wol);
    cudaGetSymbolAddress((void**)&biasp,   g_biasp);
    cudaGetSymbolAddress((void**)&hhi[0],  g_hhiA);
    cudaGetSymbolAddress((void**)&hhi[1],  g_hhiB);
    cudaGetSymbolAddress((void**)&hlo[0],  g_hloA);
    cudaGetSymbolAddress((void**)&hlo[1],  g_hloB);
    cudaGetSymbolAddress((void**)&c,       g_c);

    cudaFuncSetAttribute(lstm_gemm<true>,  cudaFuncAttributeMaxDynamicSharedMemorySize, SMEM_TOTAL);
    cudaFuncSetAttribute(lstm_gemm<false>, cudaFuncAttributeMaxDynamicSharedMemorySize, SMEM_TOTAL);

    splitTab_kernel<<<VV, 128>>>(tab);
    zero_hc_kernel<<<(BB * HH) / 256, 256>>>();
    permW_kernel<<<GG, 128>>>(W_ih, W_hh);
    permB_kernel<<<GG / 256, 256>>>(b_ih, b_hh);
    splitWout_kernel<<<NN, 128>>>(W_out);

    dim3 grid(NN / BN, BB / BM);   // (32, 8)
    for (int s = 0; s < SS; s++) {
        const int rd = s & 1, wr = (s + 1) & 1;   // ping-pong h (race fix)
        lstm_gemm<true><<<grid, 256, SMEM_TOTAL>>>(
            m, s, tabh, tabl,
            nullptr, nullptr, 0,
            wph, wpl, KTOT,
            KTOT / BK,              // 24 iters
            biasp,
            hhi[rd], hlo[rd],       // read h_s
            hhi[wr], hlo[wr],       // write h_{s+1}
            c, nullptr);
    }
    // after 128 steps (even), final h is in buffer 0
    lstm_gemm<false><<<grid, 256, SMEM_TOTAL>>>(
        nullptr, 0, nullptr, nullptr,
        hhi[0], hlo[0], HH,
        woh, wol, HH,
        HH / BK,                    // 16 iters
        b_out,
        nullptr, nullptr, nullptr, nullptr, nullptr, out);
}